// round 7
// baseline (speedup 1.0000x reference)
#include <cuda_runtime.h>

// Fixed shapes: B=64, C=3, H=W=256
#define NCAT    5
#define NB      64
#define E_ELEM  196608
#define E4      49152              // float4 positions per sample
#define TPB     256
#define K1JBLK  192                // j-chunks in K1
#define K1GRID  (NCAT * K1JBLK)    // 960
#define K2CH    48                 // j-chunks per sample in K2 (1024 f4 each)
#define K2GRID  (NB * K2CH)        // 3072
#define EPSF    1e-6f

__device__ ulonglong2 g_s[NCAT * E4];     // scale map s[c][j], packed f32x2 (~3.9MB)
__device__ float      g_upart[K1GRID];    // per-K1-block sum of U
__device__ float2     g_part2[K2GRID];    // per-K2-block (scaled, abs)
__device__ int        g_done = 0;         // K2 last-block counter (self-reset)

// -------- packed f32x2 helpers ----------------------------------------------
__device__ __forceinline__ unsigned long long f2_add(unsigned long long a, unsigned long long b) {
    unsigned long long r;
    asm("add.rn.f32x2 %0, %1, %2;" : "=l"(r) : "l"(a), "l"(b));
    return r;
}
__device__ __forceinline__ unsigned long long f2_fma(unsigned long long a, unsigned long long b,
                                                     unsigned long long c) {
    unsigned long long r;
    asm("fma.rn.f32x2 %0, %1, %2, %3;" : "=l"(r) : "l"(a), "l"(b), "l"(c));
    return r;
}
__device__ __forceinline__ void f2_unpack(unsigned long long v, float& lo, float& hi) {
    asm("mov.b64 {%0, %1}, %2;" : "=f"(lo), "=f"(hi) : "l"(v));
}
__device__ __forceinline__ unsigned long long f2_pack(float lo, float hi) {
    unsigned long long r;
    asm("mov.b64 %0, {%1, %2};" : "=l"(r) : "f"(lo), "f"(hi));
    return r;
}

#define NEG1X2 0xBF800000BF800000ULL
#define ABSM2  0x7FFFFFFF7FFFFFFFULL

__device__ __forceinline__ int clamp_cat(int c) {
    return c < 0 ? 0 : (c >= NCAT ? NCAT - 1 : c);
}

// ---------------------------------------------------------------------------
// K1: s[c][j] = 1/(U[c][j]/n_c + eps); also per-block sum of U for bn term.
// cat = bid % 5 (mixes categories across SMs to soften imbalance tail).
// ---------------------------------------------------------------------------
__global__ void __launch_bounds__(TPB)
k1_scale(const float* __restrict__ un, const int* __restrict__ de_id) {
    __shared__ int   s_id[NB];
    __shared__ int   s_off[NB];
    __shared__ int   s_n;
    __shared__ float s_ic;
    __shared__ float sred[TPB];

    const int tid = threadIdx.x;
    const int c   = blockIdx.x % NCAT;
    const int jc  = blockIdx.x / NCAT;

    if (tid < NB) s_id[tid] = clamp_cat(de_id[tid]);
    __syncthreads();
    if (tid < NB) {
        int rank = 0;
#pragma unroll
        for (int b = 0; b < NB; ++b) rank += (b < tid) && (s_id[b] == c);
        if (s_id[tid] == c) s_off[rank] = tid * E4;
    }
    if (tid == NB) {
        int n = 0;
#pragma unroll
        for (int b = 0; b < NB; ++b) n += (s_id[b] == c);
        s_n  = n;
        s_ic = 1.0f / (float)(n > 0 ? n : 1);
    }
    __syncthreads();

    const int n = s_n;
    const int j = jc * TPB + tid;
    const ulonglong2* __restrict__ up = reinterpret_cast<const ulonglong2*>(un);

    unsigned long long U0 = 0ull, U1 = 0ull;
#pragma unroll 8
    for (int k = 0; k < n; ++k) {
        ulonglong2 u = up[s_off[k] + j];
        U0 = f2_add(U0, u.x);
        U1 = f2_add(U1, u.y);
    }
    float u0, u1, u2, u3;
    f2_unpack(U0, u0, u1);
    f2_unpack(U1, u2, u3);
    const float ic = s_ic;
    float s0 = 1.0f / (u0 * ic + EPSF);
    float s1 = 1.0f / (u1 * ic + EPSF);
    float s2 = 1.0f / (u2 * ic + EPSF);
    float s3 = 1.0f / (u3 * ic + EPSF);
    ulonglong2 o;
    o.x = f2_pack(s0, s1);
    o.y = f2_pack(s2, s3);
    g_s[c * E4 + j] = o;

    // block-reduce sum of U (for bn term)
    sred[tid] = (u0 + u1) + (u2 + u3);
    __syncthreads();
#pragma unroll
    for (int st = TPB / 2; st > 0; st >>= 1) {
        if (tid < st) sred[tid] += sred[tid + st];
        __syncthreads();
    }
    if (tid == 0) g_upart[blockIdx.x] = sred[0];
}

// ---------------------------------------------------------------------------
// K2: perfectly balanced. Block = (sample b, j-chunk). Each thread: 4 iters of
// |clean-restored| with s gathered from L2-resident g_s. Last block finalizes.
// ---------------------------------------------------------------------------
__global__ void __launch_bounds__(TPB)
k2_main(const float* __restrict__ restored,
        const float* __restrict__ clean,
        const int*   __restrict__ de_id,
        float*       __restrict__ out) {
    __shared__ int   s_id[NB];
    __shared__ float swarp[2][8];
    __shared__ int   s_last;
    __shared__ float f_un[NCAT][48];
    __shared__ float f_sc[NCAT][TPB];
    __shared__ float f_ab[NCAT][TPB];

    const int tid = threadIdx.x;
    if (tid < NB) s_id[tid] = clamp_cat(de_id[tid]);
    __syncthreads();

    const int b   = blockIdx.x & 63;
    const int ch  = blockIdx.x >> 6;      // 0..47
    const int cat = s_id[b];

    const ulonglong2* __restrict__ rp = reinterpret_cast<const ulonglong2*>(restored);
    const ulonglong2* __restrict__ cp = reinterpret_cast<const ulonglong2*>(clean);
    const ulonglong2* __restrict__ sp = g_s + cat * E4;

    const int jbase = ch * 1024 + tid;
    unsigned long long SC0 = 0ull, SC1 = 0ull, AB0 = 0ull, AB1 = 0ull;
#pragma unroll
    for (int i = 0; i < 4; ++i) {
        int j   = jbase + i * TPB;
        int off = b * E4 + j;
        ulonglong2 r  = rp[off];
        ulonglong2 cl = cp[off];
        ulonglong2 sv = sp[j];
        unsigned long long d0 = f2_fma(r.x, NEG1X2, cl.x) & ABSM2;
        unsigned long long d1 = f2_fma(r.y, NEG1X2, cl.y) & ABSM2;
        AB0 = f2_add(AB0, d0);
        AB1 = f2_add(AB1, d1);
        SC0 = f2_fma(d0, sv.x, SC0);
        SC1 = f2_fma(d1, sv.y, SC1);
    }
    float x0, x1, x2, x3, y0, y1, y2, y3;
    f2_unpack(SC0, x0, x1);  f2_unpack(SC1, x2, x3);
    f2_unpack(AB0, y0, y1);  f2_unpack(AB1, y2, y3);
    float sc = (x0 + x1) + (x2 + x3);
    float ab = (y0 + y1) + (y2 + y3);

#pragma unroll
    for (int o = 16; o > 0; o >>= 1) {
        sc += __shfl_xor_sync(0xffffffffu, sc, o);
        ab += __shfl_xor_sync(0xffffffffu, ab, o);
    }
    if ((tid & 31) == 0) { swarp[0][tid >> 5] = sc; swarp[1][tid >> 5] = ab; }
    __syncthreads();
    if (tid == 0) {
        float S = 0.0f, A = 0.0f;
#pragma unroll
        for (int w = 0; w < 8; ++w) { S += swarp[0][w]; A += swarp[1][w]; }
        float2 q; q.x = S; q.y = A;
        g_part2[blockIdx.x] = q;
    }

    // ---- last-block finalize ----
    __threadfence();
    __syncthreads();
    if (tid == 0) s_last = (atomicAdd(&g_done, 1) == K2GRID - 1);
    __syncthreads();
    if (!s_last) return;
    __threadfence();

    // U totals per cat from K1 partials (idx: cat = idx % 5)
    if (tid < NCAT * 48) {
        int cc = tid / 48, g = tid % 48;
        float s = 0.0f;
#pragma unroll
        for (int r = 0; r < 4; ++r) s += __ldcg(&g_upart[cc + NCAT * (g * 4 + r)]);
        f_un[cc][g] = s;
    }
    // scaled/abs per cat from K2 partials
    {
        float lsc[NCAT], lab[NCAT];
#pragma unroll
        for (int k = 0; k < NCAT; ++k) { lsc[k] = 0.0f; lab[k] = 0.0f; }
        for (int idx = tid; idx < K2GRID; idx += TPB) {     // 12 fixed-order iters
            float2 q = __ldcg(&g_part2[idx]);
            int cc = s_id[idx & 63];
#pragma unroll
            for (int k = 0; k < NCAT; ++k) {
                lsc[k] += (cc == k) ? q.x : 0.0f;
                lab[k] += (cc == k) ? q.y : 0.0f;
            }
        }
#pragma unroll
        for (int k = 0; k < NCAT; ++k) { f_sc[k][tid] = lsc[k]; f_ab[k][tid] = lab[k]; }
    }
    __syncthreads();
#pragma unroll
    for (int st = TPB / 2; st > 0; st >>= 1) {
        if (tid < st) {
#pragma unroll
            for (int k = 0; k < NCAT; ++k) {
                f_sc[k][tid] += f_sc[k][tid + st];
                f_ab[k][tid] += f_ab[k][tid + st];
            }
        }
        __syncthreads();
    }
    __shared__ float stot_un[NCAT];
    __shared__ int   s_cnt[NCAT];
    if (tid < NCAT) {
        float s = 0.0f;
#pragma unroll
        for (int g = 0; g < 48; ++g) s += f_un[tid][g];
        stot_un[tid] = s;
        int cnt = 0;
#pragma unroll
        for (int bb = 0; bb < NB; ++bb) cnt += (s_id[bb] == tid);
        s_cnt[tid] = cnt;
    }
    __syncthreads();

    if (tid == 0) {
        const float Ef = (float)E_ELEM;
        float totalsum = 0.0f, cum_sc = 0.0f, cumN = 0.0f;
        int num_ne = 0;
#pragma unroll
        for (int cc = 0; cc < NCAT; ++cc) if (s_cnt[cc] > 0) num_ne++;
#pragma unroll
        for (int cc = 0; cc < NCAT; ++cc) {
            int   cnt  = s_cnt[cc];
            bool  ne   = cnt > 0;
            float safe = (float)(cnt > 0 ? cnt : 1);
            float S_sc = f_sc[cc][0];
            float S_ab = f_ab[cc][0];
            float S_un = stot_un[cc];

            cum_sc += S_sc;
            cumN   += (float)cnt * Ef;
            float cum_l1 = cum_sc / fmaxf(cumN, 1.0f);
            float un_num = S_un / (safe * Ef) + EPSF;
            float bn     = ne ? 2.0f * logf(un_num) : 0.0f;
            float unc    = ne ? cum_l1 : 0.0f;
            float old_l  = ne ? S_ab / (safe * Ef) : 0.0f;
            float cat_l  = unc + bn;
            totalsum += cat_l;

            out[1 + cc]  = cat_l;
            out[6 + cc]  = old_l;
            out[11 + cc] = bn;
            out[16 + cc] = unc;
        }
        out[0] = totalsum / (float)(num_ne > 0 ? num_ne : 1);
        g_done = 0;   // self-reset for graph replay
    }
}

// ---------------------------------------------------------------------------
extern "C" void kernel_launch(void* const* d_in, const int* in_sizes, int n_in,
                              void* d_out, int out_size) {
    const float* restored = (const float*)d_in[0];
    const float* clean    = (const float*)d_in[1];
    const int*   de_id    = (const int*)d_in[2];
    const float* un       = (const float*)d_in[3];
    float*       out      = (float*)d_out;

    k1_scale<<<K1GRID, TPB>>>(un, de_id);
    k2_main<<<K2GRID, TPB>>>(restored, clean, de_id, out);
}

// round 8
// speedup vs baseline: 1.2456x; 1.2456x over previous
#include <cuda_runtime.h>

// Fixed shapes: B=64, C=3, H=W=256
#define NCAT    5
#define NB      64
#define E_ELEM  196608
#define E4      49152            // float4 positions per sample
#define TPB     256
#define JBLK    192              // j-chunks: 192 * 256 = 49152
#define GRID    (NCAT * JBLK)    // 960 blocks, single wave
#define EPSF    1e-6f

__device__ float4 g_part[GRID];  // per-block (scaled, abs, un, 0)
__device__ int    g_done = 0;    // self-resetting last-block counter

// -------- packed f32x2 helpers ----------------------------------------------
__device__ __forceinline__ unsigned long long f2_add(unsigned long long a, unsigned long long b) {
    unsigned long long r;
    asm("add.rn.f32x2 %0, %1, %2;" : "=l"(r) : "l"(a), "l"(b));
    return r;
}
__device__ __forceinline__ unsigned long long f2_fma(unsigned long long a, unsigned long long b,
                                                     unsigned long long c) {
    unsigned long long r;
    asm("fma.rn.f32x2 %0, %1, %2, %3;" : "=l"(r) : "l"(a), "l"(b), "l"(c));
    return r;
}
__device__ __forceinline__ void f2_unpack(unsigned long long v, float& lo, float& hi) {
    asm("mov.b64 {%0, %1}, %2;" : "=f"(lo), "=f"(hi) : "l"(v));
}
// streaming (evict-first) 16B load
__device__ __forceinline__ ulonglong2 ldcs2(const ulonglong2* p) {
    ulonglong2 v;
    asm("ld.global.cs.v2.u64 {%0, %1}, [%2];" : "=l"(v.x), "=l"(v.y) : "l"(p));
    return v;
}

#define NEG1X2 0xBF800000BF800000ULL
#define ABSM2  0x7FFFFFFF7FFFFFFFULL

// ---------------------------------------------------------------------------
// Single kernel. Block = (category c = bid/JBLK, j-chunk). Thread (c,j)
// accumulates U[c,j] and A[c,j] over cat-c samples in one load stream.
// ---------------------------------------------------------------------------
__global__ void __launch_bounds__(TPB, 8)
k_fused(const float* __restrict__ restored,
        const float* __restrict__ clean,
        const int*   __restrict__ de_id,
        const float* __restrict__ un,
        float*       __restrict__ out) {
    __shared__ int   s_id[NB];
    __shared__ int   s_off[NB];         // this category's sample offsets (b*E4)
    __shared__ int   s_cnt[NCAT];
    __shared__ int   s_n;
    __shared__ float s_ic;
    __shared__ float swarp[3][8];
    __shared__ int   s_last;

    const int tid = threadIdx.x;
    const int c   = blockIdx.x / JBLK;
    const int jc  = blockIdx.x % JBLK;

    // ---- parallel setup: clamp ids, rank-scatter this cat's samples ----
    if (tid < NB) {
        int cc = de_id[tid];
        s_id[tid] = cc < 0 ? 0 : (cc >= NCAT ? NCAT - 1 : cc);
    }
    __syncthreads();
    if (tid < NB) {
        if (s_id[tid] == c) {
            int rank = 0;
#pragma unroll
            for (int b = 0; b < NB; ++b) rank += (b < tid) && (s_id[b] == c);
            s_off[rank] = tid * E4;
        }
    } else if (tid < NB + NCAT) {       // counts on 5 threads
        int cc = tid - NB, cnt = 0;
#pragma unroll
        for (int b = 0; b < NB; ++b) cnt += (s_id[b] == cc);
        s_cnt[cc] = cnt;
        if (cc == c) {
            s_n  = cnt;
            s_ic = 1.0f / (float)(cnt > 0 ? cnt : 1);
        }
    }
    __syncthreads();

    const int n = s_n;
    const int j = jc * TPB + tid;
    const ulonglong2* __restrict__ rp = reinterpret_cast<const ulonglong2*>(restored);
    const ulonglong2* __restrict__ cp = reinterpret_cast<const ulonglong2*>(clean);
    const ulonglong2* __restrict__ up = reinterpret_cast<const ulonglong2*>(un);

    unsigned long long U0 = 0ull, U1 = 0ull;
    unsigned long long A0 = 0ull, A1 = 0ull;
#pragma unroll 4
    for (int k = 0; k < n; ++k) {
        int off = s_off[k] + j;
        ulonglong2 u  = ldcs2(up + off);
        ulonglong2 r  = ldcs2(rp + off);
        ulonglong2 cl = ldcs2(cp + off);
        U0 = f2_add(U0, u.x);
        U1 = f2_add(U1, u.y);
        A0 = f2_add(A0, f2_fma(r.x, NEG1X2, cl.x) & ABSM2);
        A1 = f2_add(A1, f2_fma(r.y, NEG1X2, cl.y) & ABSM2);
    }

    // ---- flush: scale and dot ----
    float u0, u1, u2, u3, a0, a1, a2, a3;
    f2_unpack(U0, u0, u1);  f2_unpack(U1, u2, u3);
    f2_unpack(A0, a0, a1);  f2_unpack(A1, a2, a3);
    const float ic = s_ic;
    float s0 = 1.0f / (u0 * ic + EPSF);
    float s1 = 1.0f / (u1 * ic + EPSF);
    float s2 = 1.0f / (u2 * ic + EPSF);
    float s3 = 1.0f / (u3 * ic + EPSF);

    float vsc = fmaf(a3, s3, fmaf(a2, s2, fmaf(a1, s1, a0 * s0)));  // scaled
    float vab = (a0 + a1) + (a2 + a3);                               // abs
    float vun = (u0 + u1) + (u2 + u3);                               // un total

    // ---- warp-shuffle reduce, then 8-warp combine ----
#pragma unroll
    for (int o = 16; o > 0; o >>= 1) {
        vsc += __shfl_xor_sync(0xffffffffu, vsc, o);
        vab += __shfl_xor_sync(0xffffffffu, vab, o);
        vun += __shfl_xor_sync(0xffffffffu, vun, o);
    }
    if ((tid & 31) == 0) {
        int w = tid >> 5;
        swarp[0][w] = vsc; swarp[1][w] = vab; swarp[2][w] = vun;
    }
    __syncthreads();
    if (tid == 0) {
        float S = 0.0f, A = 0.0f, Uu = 0.0f;
#pragma unroll
        for (int w = 0; w < 8; ++w) { S += swarp[0][w]; A += swarp[1][w]; Uu += swarp[2][w]; }
        float4 q; q.x = S; q.y = A; q.z = Uu; q.w = 0.0f;
        g_part[blockIdx.x] = q;
    }

    // ---- last-block finalize (deterministic fixed-order reads) ----
    __threadfence();
    __syncthreads();
    if (tid == 0) s_last = (atomicAdd(&g_done, 1) == GRID - 1);
    __syncthreads();
    if (!s_last) return;
    __threadfence();

    __shared__ float f_sc[NCAT][48], f_ab[NCAT][48], f_un[NCAT][48];
    if (tid < NCAT * 48) {                 // 240 threads
        int cc = tid / 48, g = tid % 48;
        float sc = 0.0f, ab = 0.0f, uu = 0.0f;
#pragma unroll
        for (int r = 0; r < 4; ++r) {
            float4 q = __ldcg(&g_part[cc * JBLK + g * 4 + r]);
            sc += q.x; ab += q.y; uu += q.z;
        }
        f_sc[cc][g] = sc; f_ab[cc][g] = ab; f_un[cc][g] = uu;
    }
    __syncthreads();
    __shared__ float stot[3][NCAT];
    if (tid < NCAT) {
        float sc = 0.0f, ab = 0.0f, uu = 0.0f;
#pragma unroll
        for (int g = 0; g < 48; ++g) { sc += f_sc[tid][g]; ab += f_ab[tid][g]; uu += f_un[tid][g]; }
        stot[0][tid] = sc; stot[1][tid] = ab; stot[2][tid] = uu;
    }
    __syncthreads();

    if (tid == 0) {
        const float Ef = (float)E_ELEM;
        float totalsum = 0.0f, cum_sc = 0.0f, cumN = 0.0f;
        int num_ne = 0;
#pragma unroll
        for (int cc = 0; cc < NCAT; ++cc) if (s_cnt[cc] > 0) num_ne++;
#pragma unroll
        for (int cc = 0; cc < NCAT; ++cc) {
            int   cnt  = s_cnt[cc];
            bool  ne   = cnt > 0;
            float safe = (float)(cnt > 0 ? cnt : 1);
            float S_sc = stot[0][cc];
            float S_ab = stot[1][cc];
            float S_un = stot[2][cc];

            cum_sc += S_sc;
            cumN   += (float)cnt * Ef;
            float cum_l1 = cum_sc / fmaxf(cumN, 1.0f);
            float un_num = S_un / (safe * Ef) + EPSF;
            float bn     = ne ? 2.0f * logf(un_num) : 0.0f;
            float unc    = ne ? cum_l1 : 0.0f;
            float old_l  = ne ? S_ab / (safe * Ef) : 0.0f;
            float cat_l  = unc + bn;
            totalsum += cat_l;

            out[1 + cc]  = cat_l;
            out[6 + cc]  = old_l;
            out[11 + cc] = bn;
            out[16 + cc] = unc;
        }
        out[0] = totalsum / (float)(num_ne > 0 ? num_ne : 1);
        g_done = 0;   // self-reset for graph replay
    }
}

// ---------------------------------------------------------------------------
extern "C" void kernel_launch(void* const* d_in, const int* in_sizes, int n_in,
                              void* d_out, int out_size) {
    const float* restored = (const float*)d_in[0];
    const float* clean    = (const float*)d_in[1];
    const int*   de_id    = (const int*)d_in[2];
    const float* un       = (const float*)d_in[3];
    float*       out      = (float*)d_out;

    k_fused<<<GRID, TPB>>>(restored, clean, de_id, un, out);
}